// round 2
// baseline (speedup 1.0000x reference)
#include <cuda_runtime.h>

// UWNeRF RGB renderer: R=65536 rays, S=128 samples.
// Warp-per-ray. Lane l owns contiguous samples [4l, 4l+3] -> every global load
// is a coalesced float4 (LDG.E.128). 7 exclusive prefix sums via warp shfl scan.
// Outputs: (rgb, restored, direct, backscatter), each [R,3], concatenated.

#define NUM_R 65536
#define NUM_S 128

__device__ __forceinline__ float clip01(float x) { return __saturatef(x); }

// Exclusive prefix sum over 128 samples distributed 4-per-lane (contiguous).
__device__ __forceinline__ void warp_excl_scan4(const float v[4], float excl[4], int lane) {
    float p0 = v[0];
    float p1 = p0 + v[1];
    float p2 = p1 + v[2];
    float p3 = p2 + v[3];
    float x = p3;
    #pragma unroll
    for (int off = 1; off < 32; off <<= 1) {
        float y = __shfl_up_sync(0xffffffffu, x, off);
        x += (lane >= off) ? y : 0.0f;
    }
    float le = x - p3;  // exclusive prefix of this lane's 4-sample block
    excl[0] = le;
    excl[1] = le + p0;
    excl[2] = le + p1;
    excl[3] = le + p2;
}

__global__ __launch_bounds__(128)
void uwnerf_render_kernel(
    const float* __restrict__ densities,     // [R,S,1]
    const float* __restrict__ rgbs,          // [R,S,3]
    const float* __restrict__ veiling,       // [R,S,3]
    const float* __restrict__ direct_coeffs, // [R,S,3]
    const float* __restrict__ backsc_coeffs, // [R,S,3]
    const float* __restrict__ deltas,        // [R,S,1]
    float* __restrict__ out)                 // [4, R, 3]
{
    // Grid exactly covers NUM_R rays: no early exit anywhere (all shfls are
    // executed by full warps -> provably convergent).
    const int r    = (blockIdx.x * blockDim.x + threadIdx.x) >> 5;
    const int lane = threadIdx.x & 31;

    // ---- scalar arrays: lane loads 4 contiguous samples as one float4 ----
    const float4 dl = reinterpret_cast<const float4*>(deltas    + (size_t)r * NUM_S)[lane];
    const float4 de = reinterpret_cast<const float4*>(densities + (size_t)r * NUM_S)[lane];
    float dlt[4] = {dl.x, dl.y, dl.z, dl.w};
    float dd[4]  = {dl.x * de.x, dl.y * de.y, dl.z * de.z, dl.w * de.w};

    // ---- 3-channel arrays: 12 contiguous floats per lane (3 x float4) ----
    const size_t cbase = ((size_t)r * NUM_S) * 3 + (size_t)lane * 12;

    float rgbv[12], veilv[12];
    {
        const float4* p = reinterpret_cast<const float4*>(rgbs + cbase);
        *reinterpret_cast<float4*>(&rgbv[0]) = p[0];
        *reinterpret_cast<float4*>(&rgbv[4]) = p[1];
        *reinterpret_cast<float4*>(&rgbv[8]) = p[2];
        p = reinterpret_cast<const float4*>(veiling + cbase);
        *reinterpret_cast<float4*>(&veilv[0]) = p[0];
        *reinterpret_cast<float4*>(&veilv[4]) = p[1];
        *reinterpret_cast<float4*>(&veilv[8]) = p[2];
    }

    // ---- object transmittance / weights ----
    float ex[4];
    warp_excl_scan4(dd, ex, lane);

    float w[4];
    float wsum = 0.0f;
    float rest[3] = {0.0f, 0.0f, 0.0f};
    #pragma unroll
    for (int j = 0; j < 4; j++) {
        float T     = __expf(-ex[j]);
        float alpha = 1.0f - __expf(-dd[j]);
        w[j] = alpha * T;
        wsum += w[j];
        rest[0] += w[j] * rgbv[j * 3 + 0];
        rest[1] += w[j] * rgbv[j * 3 + 1];
        rest[2] += w[j] * rgbv[j * 3 + 2];
    }

    // ---- direct attenuation: 3 scans over delta*direct_coeffs ----
    float dir[3] = {0.0f, 0.0f, 0.0f};
    {
        float dircv[12];
        const float4* p = reinterpret_cast<const float4*>(direct_coeffs + cbase);
        *reinterpret_cast<float4*>(&dircv[0]) = p[0];
        *reinterpret_cast<float4*>(&dircv[4]) = p[1];
        *reinterpret_cast<float4*>(&dircv[8]) = p[2];
        #pragma unroll
        for (int c = 0; c < 3; c++) {
            float v[4], e[4];
            #pragma unroll
            for (int j = 0; j < 4; j++) v[j] = dlt[j] * dircv[j * 3 + c];
            warp_excl_scan4(v, e, lane);
            #pragma unroll
            for (int j = 0; j < 4; j++)
                dir[c] += w[j] * __expf(-e[j]) * rgbv[j * 3 + c];
        }
    }

    // ---- backscatter attenuation: 3 scans over delta*backscatter_coeffs ----
    float obs[3] = {0.0f, 0.0f, 0.0f};
    {
        float bscv[12];
        const float4* p = reinterpret_cast<const float4*>(backsc_coeffs + cbase);
        *reinterpret_cast<float4*>(&bscv[0]) = p[0];
        *reinterpret_cast<float4*>(&bscv[4]) = p[1];
        *reinterpret_cast<float4*>(&bscv[8]) = p[2];
        #pragma unroll
        for (int c = 0; c < 3; c++) {
            float v[4], e[4];
            #pragma unroll
            for (int j = 0; j < 4; j++) v[j] = dlt[j] * bscv[j * 3 + c];
            warp_excl_scan4(v, e, lane);
            #pragma unroll
            for (int j = 0; j < 4; j++)
                obs[c] += w[j] * (1.0f - __expf(-e[j])) * veilv[j * 3 + c];
        }
    }

    // ---- warp reductions (10 accumulators) ----
    #pragma unroll
    for (int off = 16; off > 0; off >>= 1) {
        wsum += __shfl_down_sync(0xffffffffu, wsum, off);
        #pragma unroll
        for (int c = 0; c < 3; c++) {
            rest[c] += __shfl_down_sync(0xffffffffu, rest[c], off);
            dir[c]  += __shfl_down_sync(0xffffffffu, dir[c], off);
            obs[c]  += __shfl_down_sync(0xffffffffu, obs[c], off);
        }
    }

    // ---- lane 0 owns sample 0 (veiling_light[:,0,:]) and writes outputs ----
    if (lane == 0) {
        const float omask = clip01(wsum);
        const size_t RT3 = (size_t)NUM_R * 3;
        #pragma unroll
        for (int c = 0; c < 3; c++) {
            float medium = (1.0f - omask) * veilv[c];  // veiling at s=0
            float bs_ray = obs[c] + medium;
            out[0 * RT3 + (size_t)r * 3 + c] = clip01(dir[c] + bs_ray);  // rgb
            out[1 * RT3 + (size_t)r * 3 + c] = clip01(rest[c]);          // restored
            out[2 * RT3 + (size_t)r * 3 + c] = clip01(dir[c]);           // direct
            out[3 * RT3 + (size_t)r * 3 + c] = clip01(bs_ray);           // backscatter
        }
    }
}

extern "C" void kernel_launch(void* const* d_in, const int* in_sizes, int n_in,
                              void* d_out, int out_size) {
    const float* densities     = (const float*)d_in[0];
    const float* rgbs          = (const float*)d_in[1];
    const float* veiling       = (const float*)d_in[2];
    const float* direct_coeffs = (const float*)d_in[3];
    const float* backsc_coeffs = (const float*)d_in[4];
    const float* deltas        = (const float*)d_in[5];
    float* out = (float*)d_out;

    // 4 warps (4 rays) per 128-thread block -> 16384 blocks, exact cover.
    const int threads = 128;
    const int blocks  = (NUM_R * 32) / threads;
    uwnerf_render_kernel<<<blocks, threads>>>(
        densities, rgbs, veiling, direct_coeffs, backsc_coeffs, deltas, out);
}